// round 4
// baseline (speedup 1.0000x reference)
#include <cuda_runtime.h>

// RNN: B=4096, T=1024, H=64, scalar input, C=5 head.
//   h_{t+1}[b,i] = tanh(x[b,t]*w_ih[i] + b_ih[i] + b_hh[i] + sum_j h_t[b,j]*w_hh[i,j])
//   out[b,c]     = sum_j hT[b,j]*w_head[c,j] + b_head[c]
//
// R2 design: f32x2 packed along j (horizontal-add epilogue), natural W/h
// layouts (no duplication), 256 threads/CTA (2 warps/SMSP), padded SMEM
// strides for zero bank conflicts, double-buffered h, 1 barrier/step.

#define BB 4096
#define TT 1024
#define HH 64
#define CC 5
#define NB 32            // batches per CTA
#define NTHREADS 256
#define TCH 32           // x staging chunk (timesteps)
#define WSTRIDE 68       // floats per W row  (bank shift 4/row)
#define HSTRIDE 72       // floats per h row  (bank shift 8/batch)

typedef unsigned long long u64;

__device__ __forceinline__ u64 fma2(u64 a, u64 b, u64 c) {
    u64 d; asm("fma.rn.f32x2 %0, %1, %2, %3;" : "=l"(d) : "l"(a), "l"(b), "l"(c)); return d;
}
__device__ __forceinline__ float2 up2(u64 v) {
    float2 f; asm("mov.b64 {%0,%1}, %2;" : "=f"(f.x), "=f"(f.y) : "l"(v)); return f;
}
__device__ __forceinline__ float ftanh(float xv) {
    // tanh(x) = 1 - 2/(e^{2x}+1); exact at saturation via inf.
    float e = __expf(2.0f * xv);
    return 1.0f - __fdividef(2.0f, e + 1.0f);
}

extern "C" __global__ void __launch_bounds__(NTHREADS, 1)
rnn_jpack_kernel(const float* __restrict__ x,
                 const float* __restrict__ w_ih,
                 const float* __restrict__ b_ih,
                 const float* __restrict__ w_hh,
                 const float* __restrict__ b_hh,
                 const float* __restrict__ w_head,
                 const float* __restrict__ b_head,
                 float* __restrict__ out)
{
    __shared__ __align__(16) float ws[HH * WSTRIDE];      // 17408 B
    __shared__ __align__(16) float hs[2][NB * HSTRIDE];   // 18432 B
    __shared__ float xs[TCH * NB];                        //  4096 B

    const int tid  = threadIdx.x;
    const int b0   = blockIdx.x * NB;
    const int lane = tid & 31;
    const int wrp  = tid >> 5;

    // warp tile: 32 rows x 8 batches; thread tile: 4 rows x 2 batches
    const int bg = lane & 3;               // batch group (4 distinct/warp)
    const int rr = lane >> 2;              // row group   (8 distinct/warp)
    const int warp_row0 = (wrp & 1) * 32;  // 2 row-halves
    const int warp_b0   = (wrp >> 1) * 8;  // 4 batch-groups
    const int bl0 = warp_b0 + bg;          // local batches
    const int bl1 = bl0 + 4;
    const int r0  = warp_row0 + rr;        // rows r0 + {0,8,16,24}

    // --- stage W (natural [row][j], padded stride) ---
    for (int e = tid; e < HH * HH; e += NTHREADS) {
        int i = e >> 6, j = e & 63;
        ws[i * WSTRIDE + j] = w_hh[e];
    }
    // --- zero h buffer 0 ---
    for (int e = tid; e < NB * HSTRIDE; e += NTHREADS) hs[0][e] = 0.0f;

    // --- per-thread row constants ---
    float wihv[4], biasv[4];
#pragma unroll
    for (int ri = 0; ri < 4; ri++) {
        int i = r0 + 8 * ri;
        wihv[ri]  = w_ih[i];
        biasv[ri] = b_ih[i] + b_hh[i];
    }
    __syncthreads();

    // W row pointers (quad-granular)
    const ulonglong2* wq[4];
#pragma unroll
    for (int ri = 0; ri < 4; ri++)
        wq[ri] = (const ulonglong2*)(ws + (r0 + 8 * ri) * WSTRIDE);

    int cur = 0;
    for (int t = 0; t < TT; t++) {
        const int tc = t & (TCH - 1);
        if (tc == 0) {
            // stage x[b0..b0+31][t..t+TCH): coalesced per local batch
            for (int e = tid; e < NB * TCH; e += NTHREADS) {
                int r = e >> 5, tcol = e & (TCH - 1);
                xs[tcol * NB + r] = x[(size_t)(b0 + r) * TT + t + tcol];
            }
            __syncthreads();
        }

        const float* hcur = hs[cur];
        float*       hnxt = hs[cur ^ 1];
        const ulonglong2* hq0 = (const ulonglong2*)(hcur + bl0 * HSTRIDE);
        const ulonglong2* hq1 = (const ulonglong2*)(hcur + bl1 * HSTRIDE);

        const float xb0 = xs[tc * NB + bl0];
        const float xb1 = xs[tc * NB + bl1];

        u64 acc[2][4];
#pragma unroll
        for (int ri = 0; ri < 4; ri++) { acc[0][ri] = 0ull; acc[1][ri] = 0ull; }

#pragma unroll
        for (int q = 0; q < 16; q++) {          // j = 4q .. 4q+3
            ulonglong2 h0 = hq0[q];             // {h[j],h[j+1]},{h[j+2],h[j+3]} b=bl0
            ulonglong2 h1 = hq1[q];
#pragma unroll
            for (int ri = 0; ri < 4; ri++) {
                ulonglong2 wv = wq[ri][q];      // {w[j],w[j+1]},{w[j+2],w[j+3]}
                acc[0][ri] = fma2(wv.x, h0.x, acc[0][ri]);
                acc[1][ri] = fma2(wv.x, h1.x, acc[1][ri]);
                acc[0][ri] = fma2(wv.y, h0.y, acc[0][ri]);
                acc[1][ri] = fma2(wv.y, h1.y, acc[1][ri]);
            }
        }

        // epilogue: horizontal add + input/bias + tanh + store
#pragma unroll
        for (int bi = 0; bi < 2; bi++) {
            const int   bl = bi ? bl1 : bl0;
            const float xb = bi ? xb1 : xb0;
#pragma unroll
            for (int ri = 0; ri < 4; ri++) {
                float2 a = up2(acc[bi][ri]);
                float  s = a.x + a.y + fmaf(xb, wihv[ri], biasv[ri]);
                hnxt[bl * HSTRIDE + r0 + 8 * ri] = ftanh(s);
            }
        }
        __syncthreads();
        cur ^= 1;
    }

    // --- head: out[b,c] = sum_j h[b,j]*w_head[c,j] + b_head[c] ---
    if (tid < NB) {
        const float* hfin = hs[cur] + tid * HSTRIDE;
        float s[CC];
#pragma unroll
        for (int c = 0; c < CC; c++) s[c] = b_head[c];
        for (int j = 0; j < HH; j++) {
            float hv = hfin[j];
#pragma unroll
            for (int c = 0; c < CC; c++) s[c] = fmaf(hv, w_head[c * HH + j], s[c]);
        }
#pragma unroll
        for (int c = 0; c < CC; c++) out[(size_t)(b0 + tid) * CC + c] = s[c];
    }
}

extern "C" void kernel_launch(void* const* d_in, const int* in_sizes, int n_in,
                              void* d_out, int out_size)
{
    (void)in_sizes; (void)n_in; (void)out_size;
    const float* x      = (const float*)d_in[0];
    const float* w_ih   = (const float*)d_in[1];
    const float* b_ih   = (const float*)d_in[2];
    const float* w_hh   = (const float*)d_in[3];
    const float* b_hh   = (const float*)d_in[4];
    const float* w_head = (const float*)d_in[5];
    const float* b_head = (const float*)d_in[6];
    float* out = (float*)d_out;

    rnn_jpack_kernel<<<BB / NB, NTHREADS>>>(
        x, w_ih, b_ih, w_hh, b_hh, w_head, b_head, out);
}

// round 5
// speedup vs baseline: 1.0000x; 1.0000x over previous
#include <cuda_runtime.h>

// RNN: B=4096, T=1024, H=64, scalar input, C=5 head.
//   h_{t+1}[b,i] = tanh(x[b,t]*w_ih[i] + b_ih[i] + b_hh[i] + sum_j h_t[b,j]*w_hh[i,j])
//   out[b,c]     = sum_j hT[b,j]*w_head[c,j] + b_head[c]
//
// R2 design: f32x2 packed along j (horizontal-add epilogue), natural W/h
// layouts (no duplication), 256 threads/CTA (2 warps/SMSP), padded SMEM
// strides for zero bank conflicts, double-buffered h, 1 barrier/step.

#define BB 4096
#define TT 1024
#define HH 64
#define CC 5
#define NB 32            // batches per CTA
#define NTHREADS 256
#define TCH 32           // x staging chunk (timesteps)
#define WSTRIDE 68       // floats per W row  (bank shift 4/row)
#define HSTRIDE 72       // floats per h row  (bank shift 8/batch)

typedef unsigned long long u64;

__device__ __forceinline__ u64 fma2(u64 a, u64 b, u64 c) {
    u64 d; asm("fma.rn.f32x2 %0, %1, %2, %3;" : "=l"(d) : "l"(a), "l"(b), "l"(c)); return d;
}
__device__ __forceinline__ float2 up2(u64 v) {
    float2 f; asm("mov.b64 {%0,%1}, %2;" : "=f"(f.x), "=f"(f.y) : "l"(v)); return f;
}
__device__ __forceinline__ float ftanh(float xv) {
    // tanh(x) = 1 - 2/(e^{2x}+1); exact at saturation via inf.
    float e = __expf(2.0f * xv);
    return 1.0f - __fdividef(2.0f, e + 1.0f);
}

extern "C" __global__ void __launch_bounds__(NTHREADS, 1)
rnn_jpack_kernel(const float* __restrict__ x,
                 const float* __restrict__ w_ih,
                 const float* __restrict__ b_ih,
                 const float* __restrict__ w_hh,
                 const float* __restrict__ b_hh,
                 const float* __restrict__ w_head,
                 const float* __restrict__ b_head,
                 float* __restrict__ out)
{
    __shared__ __align__(16) float ws[HH * WSTRIDE];      // 17408 B
    __shared__ __align__(16) float hs[2][NB * HSTRIDE];   // 18432 B
    __shared__ float xs[TCH * NB];                        //  4096 B

    const int tid  = threadIdx.x;
    const int b0   = blockIdx.x * NB;
    const int lane = tid & 31;
    const int wrp  = tid >> 5;

    // warp tile: 32 rows x 8 batches; thread tile: 4 rows x 2 batches
    const int bg = lane & 3;               // batch group (4 distinct/warp)
    const int rr = lane >> 2;              // row group   (8 distinct/warp)
    const int warp_row0 = (wrp & 1) * 32;  // 2 row-halves
    const int warp_b0   = (wrp >> 1) * 8;  // 4 batch-groups
    const int bl0 = warp_b0 + bg;          // local batches
    const int bl1 = bl0 + 4;
    const int r0  = warp_row0 + rr;        // rows r0 + {0,8,16,24}

    // --- stage W (natural [row][j], padded stride) ---
    for (int e = tid; e < HH * HH; e += NTHREADS) {
        int i = e >> 6, j = e & 63;
        ws[i * WSTRIDE + j] = w_hh[e];
    }
    // --- zero h buffer 0 ---
    for (int e = tid; e < NB * HSTRIDE; e += NTHREADS) hs[0][e] = 0.0f;

    // --- per-thread row constants ---
    float wihv[4], biasv[4];
#pragma unroll
    for (int ri = 0; ri < 4; ri++) {
        int i = r0 + 8 * ri;
        wihv[ri]  = w_ih[i];
        biasv[ri] = b_ih[i] + b_hh[i];
    }
    __syncthreads();

    // W row pointers (quad-granular)
    const ulonglong2* wq[4];
#pragma unroll
    for (int ri = 0; ri < 4; ri++)
        wq[ri] = (const ulonglong2*)(ws + (r0 + 8 * ri) * WSTRIDE);

    int cur = 0;
    for (int t = 0; t < TT; t++) {
        const int tc = t & (TCH - 1);
        if (tc == 0) {
            // stage x[b0..b0+31][t..t+TCH): coalesced per local batch
            for (int e = tid; e < NB * TCH; e += NTHREADS) {
                int r = e >> 5, tcol = e & (TCH - 1);
                xs[tcol * NB + r] = x[(size_t)(b0 + r) * TT + t + tcol];
            }
            __syncthreads();
        }

        const float* hcur = hs[cur];
        float*       hnxt = hs[cur ^ 1];
        const ulonglong2* hq0 = (const ulonglong2*)(hcur + bl0 * HSTRIDE);
        const ulonglong2* hq1 = (const ulonglong2*)(hcur + bl1 * HSTRIDE);

        const float xb0 = xs[tc * NB + bl0];
        const float xb1 = xs[tc * NB + bl1];

        u64 acc[2][4];
#pragma unroll
        for (int ri = 0; ri < 4; ri++) { acc[0][ri] = 0ull; acc[1][ri] = 0ull; }

#pragma unroll
        for (int q = 0; q < 16; q++) {          // j = 4q .. 4q+3
            ulonglong2 h0 = hq0[q];             // {h[j],h[j+1]},{h[j+2],h[j+3]} b=bl0
            ulonglong2 h1 = hq1[q];
#pragma unroll
            for (int ri = 0; ri < 4; ri++) {
                ulonglong2 wv = wq[ri][q];      // {w[j],w[j+1]},{w[j+2],w[j+3]}
                acc[0][ri] = fma2(wv.x, h0.x, acc[0][ri]);
                acc[1][ri] = fma2(wv.x, h1.x, acc[1][ri]);
                acc[0][ri] = fma2(wv.y, h0.y, acc[0][ri]);
                acc[1][ri] = fma2(wv.y, h1.y, acc[1][ri]);
            }
        }

        // epilogue: horizontal add + input/bias + tanh + store
#pragma unroll
        for (int bi = 0; bi < 2; bi++) {
            const int   bl = bi ? bl1 : bl0;
            const float xb = bi ? xb1 : xb0;
#pragma unroll
            for (int ri = 0; ri < 4; ri++) {
                float2 a = up2(acc[bi][ri]);
                float  s = a.x + a.y + fmaf(xb, wihv[ri], biasv[ri]);
                hnxt[bl * HSTRIDE + r0 + 8 * ri] = ftanh(s);
            }
        }
        __syncthreads();
        cur ^= 1;
    }

    // --- head: out[b,c] = sum_j h[b,j]*w_head[c,j] + b_head[c] ---
    if (tid < NB) {
        const float* hfin = hs[cur] + tid * HSTRIDE;
        float s[CC];
#pragma unroll
        for (int c = 0; c < CC; c++) s[c] = b_head[c];
        for (int j = 0; j < HH; j++) {
            float hv = hfin[j];
#pragma unroll
            for (int c = 0; c < CC; c++) s[c] = fmaf(hv, w_head[c * HH + j], s[c]);
        }
#pragma unroll
        for (int c = 0; c < CC; c++) out[(size_t)(b0 + tid) * CC + c] = s[c];
    }
}

extern "C" void kernel_launch(void* const* d_in, const int* in_sizes, int n_in,
                              void* d_out, int out_size)
{
    (void)in_sizes; (void)n_in; (void)out_size;
    const float* x      = (const float*)d_in[0];
    const float* w_ih   = (const float*)d_in[1];
    const float* b_ih   = (const float*)d_in[2];
    const float* w_hh   = (const float*)d_in[3];
    const float* b_hh   = (const float*)d_in[4];
    const float* w_head = (const float*)d_in[5];
    const float* b_head = (const float*)d_in[6];
    float* out = (float*)d_out;

    rnn_jpack_kernel<<<BB / NB, NTHREADS>>>(
        x, w_ih, b_ih, w_hh, b_hh, w_head, b_head, out);
}

// round 6
// speedup vs baseline: 1.3725x; 1.3724x over previous
#include <cuda_runtime.h>

// RNN: B=4096, T=1024, H=64, scalar input, C=5 head.
//   h_{t+1}[b,i] = tanh(x[b,t]*w_ih[i] + b_ih[i] + b_hh[i] + sum_j h_t[b,j]*w_hh[i,j])
//   out[b,c]     = sum_j hT[b,j]*w_head[c,j] + b_head[c]
//
// R5 design: W_hh entirely in registers (2 rows/lane x 32 j-pairs = 128 regs),
// h broadcast from SMEM (1 wavefront per LDS.128), f32x2 packed along j,
// warp-private batches => NO block barrier in the time loop (syncwarp only),
// x via register chunks + shuffle with 32-step prefetch.

#define BB 4096
#define TT 1024
#define HH 64
#define CC 5
#define NB 32            // batches per CTA
#define NTHREADS 256     // 8 warps
#define BPW 4            // batches per warp

typedef unsigned long long u64;

__device__ __forceinline__ u64 fma2(u64 a, u64 b, u64 c) {
    u64 d; asm("fma.rn.f32x2 %0, %1, %2, %3;" : "=l"(d) : "l"(a), "l"(b), "l"(c)); return d;
}
__device__ __forceinline__ float2 up2(u64 v) {
    float2 f; asm("mov.b64 {%0,%1}, %2;" : "=f"(f.x), "=f"(f.y) : "l"(v)); return f;
}
__device__ __forceinline__ float ftanh(float xv) {
    // tanh(x) = 1 - 2/(e^{2x}+1); exact at saturation via inf.
    float e = __expf(2.0f * xv);
    return 1.0f - __fdividef(2.0f, e + 1.0f);
}

extern "C" __global__ void __launch_bounds__(NTHREADS, 1)
rnn_wreg_kernel(const float* __restrict__ x,
                const float* __restrict__ w_ih,
                const float* __restrict__ b_ih,
                const float* __restrict__ w_hh,
                const float* __restrict__ b_hh,
                const float* __restrict__ w_head,
                const float* __restrict__ b_head,
                float* __restrict__ out)
{
    __shared__ __align__(16) float hs[2][NB][HH];   // 16 KB, double-buffered h

    const int tid  = threadIdx.x;
    const int lane = tid & 31;
    const int wrp  = tid >> 5;
    const int b0   = wrp * BPW;                  // local batch base (warp-private)
    const int gb   = blockIdx.x * NB + b0;       // global batch base
    const int row0 = lane;
    const int row1 = lane + 32;

    // --- W_hh rows {lane, lane+32} into registers, packed as j-pairs ---
    u64 wreg0[32], wreg1[32];
    {
        const u64* wr0 = (const u64*)(w_hh + (size_t)row0 * HH);
        const u64* wr1 = (const u64*)(w_hh + (size_t)row1 * HH);
#pragma unroll
        for (int jp = 0; jp < 32; jp++) { wreg0[jp] = wr0[jp]; wreg1[jp] = wr1[jp]; }
    }
    const float wih0 = w_ih[row0], wih1 = w_ih[row1];
    const float bia0 = b_ih[row0] + b_hh[row0];
    const float bia1 = b_ih[row1] + b_hh[row1];

    // --- zero h buffer 0 for this warp's batches ---
#pragma unroll
    for (int k = 0; k < BPW; k++) {
        hs[0][b0 + k][row0] = 0.0f;
        hs[0][b0 + k][row1] = 0.0f;
    }
    __syncwarp();

    // --- x chunking: lane holds x[b][t0+lane]; prefetch next chunk ---
    float xcur[BPW], xnxt[BPW];
#pragma unroll
    for (int k = 0; k < BPW; k++) xnxt[k] = x[(size_t)(gb + k) * TT + lane];

    int cur = 0;
    for (int t = 0; t < TT; t++) {
        const int tc = t & 31;
        if (tc == 0) {
#pragma unroll
            for (int k = 0; k < BPW; k++) xcur[k] = xnxt[k];
            if (t + 32 < TT) {
#pragma unroll
                for (int k = 0; k < BPW; k++)
                    xnxt[k] = x[(size_t)(gb + k) * TT + (t + 32) + lane];
            }
        }

        const ulonglong2* hb0 = (const ulonglong2*)hs[cur][b0 + 0];
        const ulonglong2* hb1 = (const ulonglong2*)hs[cur][b0 + 1];
        const ulonglong2* hb2 = (const ulonglong2*)hs[cur][b0 + 2];
        const ulonglong2* hb3 = (const ulonglong2*)hs[cur][b0 + 3];

        u64 acc0[BPW], acc1[BPW];
#pragma unroll
        for (int k = 0; k < BPW; k++) { acc0[k] = 0ull; acc1[k] = 0ull; }

#pragma unroll
        for (int q = 0; q < 16; q++) {
            // broadcast loads: all lanes read the same 16B of h => 1 wavefront
            ulonglong2 h0 = hb0[q];
            ulonglong2 h1 = hb1[q];
            ulonglong2 h2 = hb2[q];
            ulonglong2 h3 = hb3[q];
            const u64 wa0 = wreg0[2*q], wb0 = wreg0[2*q + 1];
            const u64 wa1 = wreg1[2*q], wb1 = wreg1[2*q + 1];
            acc0[0] = fma2(wa0, h0.x, acc0[0]);
            acc0[1] = fma2(wa0, h1.x, acc0[1]);
            acc0[2] = fma2(wa0, h2.x, acc0[2]);
            acc0[3] = fma2(wa0, h3.x, acc0[3]);
            acc1[0] = fma2(wa1, h0.x, acc1[0]);
            acc1[1] = fma2(wa1, h1.x, acc1[1]);
            acc1[2] = fma2(wa1, h2.x, acc1[2]);
            acc1[3] = fma2(wa1, h3.x, acc1[3]);
            acc0[0] = fma2(wb0, h0.y, acc0[0]);
            acc0[1] = fma2(wb0, h1.y, acc0[1]);
            acc0[2] = fma2(wb0, h2.y, acc0[2]);
            acc0[3] = fma2(wb0, h3.y, acc0[3]);
            acc1[0] = fma2(wb1, h0.y, acc1[0]);
            acc1[1] = fma2(wb1, h1.y, acc1[1]);
            acc1[2] = fma2(wb1, h2.y, acc1[2]);
            acc1[3] = fma2(wb1, h3.y, acc1[3]);
        }

        // epilogue: horizontal add + input/bias + tanh + coalesced store
        float* hn = (float*)hs[cur ^ 1];
#pragma unroll
        for (int k = 0; k < BPW; k++) {
            float xv = __shfl_sync(0xffffffffu, xcur[k], tc);
            float2 a0 = up2(acc0[k]);
            float2 a1 = up2(acc1[k]);
            float s0 = a0.x + a0.y + fmaf(xv, wih0, bia0);
            float s1 = a1.x + a1.y + fmaf(xv, wih1, bia1);
            hn[(b0 + k) * HH + row0] = ftanh(s0);
            hn[(b0 + k) * HH + row1] = ftanh(s1);
        }
        __syncwarp();
        cur ^= 1;
    }

    // --- head: out[b,c] = sum_j h[b,j]*w_head[c,j] + b_head[c] ---
    // warp-private: lanes 0..19 each handle one (batch k, class c)
    if (lane < BPW * CC) {
        const int k = lane / CC;
        const int c = lane % CC;
        const float* hf = hs[cur][b0 + k];
        float s = b_head[c];
#pragma unroll
        for (int j = 0; j < HH; j++)
            s = fmaf(hf[j], w_head[c * HH + j], s);
        out[(size_t)(gb + k) * CC + c] = s;
    }
}

extern "C" void kernel_launch(void* const* d_in, const int* in_sizes, int n_in,
                              void* d_out, int out_size)
{
    (void)in_sizes; (void)n_in; (void)out_size;
    const float* x      = (const float*)d_in[0];
    const float* w_ih   = (const float*)d_in[1];
    const float* b_ih   = (const float*)d_in[2];
    const float* w_hh   = (const float*)d_in[3];
    const float* b_hh   = (const float*)d_in[4];
    const float* w_head = (const float*)d_in[5];
    const float* b_head = (const float*)d_in[6];
    float* out = (float*)d_out;

    rnn_wreg_kernel<<<BB / NB, NTHREADS>>>(
        x, w_ih, b_ih, w_hh, b_hh, w_head, b_head, out);
}